// round 3
// baseline (speedup 1.0000x reference)
#include <cuda_runtime.h>
#include <cuda_fp16.h>
#include <cstdint>

// Problem constants (fixed by the dataset)
#define BB 4
#define NN 50000
#define RR 100000
#define EE 1600000
#define D1 32
#define D2 16
#define NEG 0.2f

// Bucket capacities (Poisson lambda=16 R-rows / 32 N-rows; overflow prob < 1e-25)
#define CAP_T1 128
#define CAP_X1 192
#define CAP_T2 128
#define CAP_P1 256

#define MW_R ((RR + 31) / 32)
#define MW_N ((NN + 31) / 32)

// ---------------- device scratch ----------------
// layouts: [node][batch][d] so one edge-gather touches one contiguous region
__device__ __half g_h1[NN * BB * D1];  // 12.8 MB (fp16 to halve k_T1 gather traffic)
__device__ float g_T1[RR * BB * D1];   // 51.2 MB
__device__ float g_h2[NN * BB * D2];   // 12.8 MB
__device__ float g_T2[RR * BB * D2];   // 25.6 MB

__device__ int  g_cntT1[RR], g_cntX1[NN], g_cntT2[RR], g_cntP1[2];
__device__ int2 g_bT1[RR * CAP_T1];    // (col, val)
__device__ int2 g_bX1[NN * CAP_X1];    // (col, coef)
__device__ int2 g_bT2[RR * CAP_T2];    // (col, val)
__device__ int2 g_bP1[2 * CAP_P1];     // (col, coef)

__device__ unsigned g_mT1[MW_R], g_mT2[MW_R], g_mH2[MW_N];   // bit flags
__device__ int g_listT1[RR], g_listX1[NN], g_listT2[RR];
__device__ int g_nT1, g_nX1, g_nT2;

// ---------------- reset per call ----------------
__global__ void k_zero() {
    int i = blockIdx.x * blockDim.x + threadIdx.x;
    int stride = gridDim.x * blockDim.x;
    for (int j = i; j < RR; j += stride) { g_cntT1[j] = 0; g_cntT2[j] = 0; }
    for (int j = i; j < NN; j += stride) g_cntX1[j] = 0;
    for (int j = i; j < MW_R; j += stride) { g_mT1[j] = 0u; g_mT2[j] = 0u; }
    for (int j = i; j < MW_N; j += stride) g_mH2[j] = 0u;
    if (i < 2) g_cntP1[i] = 0;
    if (i == 0) { g_nT1 = 0; g_nX1 = 0; g_nT2 = 0; }
}

// ---------------- backward pruning scans (16 edges / thread, loads batched) ----------------
__global__ void k_p1(const int* __restrict__ wiRows, const int* __restrict__ wiCols,
                     const float* __restrict__ wiVals, const float* __restrict__ diag2) {
    int base = (blockIdx.x * blockDim.x + threadIdx.x) * 16;
    if (base >= EE) return;
    const int4* rp = (const int4*)(wiRows + base);
    int4 r[4];
    r[0] = rp[0]; r[1] = rp[1]; r[2] = rp[2]; r[3] = rp[3];
    const int* rr = (const int*)r;
#pragma unroll
    for (int j = 0; j < 16; j++) {
        int rv = rr[j];
        if (rv >= NN - 2) {
            int s = rv - (NN - 2);
            int e = base + j;
            int col = wiCols[e];
            float coef = wiVals[e] * diag2[col];
            int slot = atomicAdd(&g_cntP1[s], 1);
            if (slot < CAP_P1) g_bP1[s * CAP_P1 + slot] = make_int2(col, __float_as_int(coef));
            atomicOr(&g_mT2[col >> 5], 1u << (col & 31));
        }
    }
}

__global__ void k_p2(const int* __restrict__ wRows, const int* __restrict__ wCols,
                     const float* __restrict__ wVals) {
    int base = (blockIdx.x * blockDim.x + threadIdx.x) * 16;
    if (base >= EE) return;
    const int4* rp = (const int4*)(wRows + base);
    int4 r[4];
    r[0] = rp[0]; r[1] = rp[1]; r[2] = rp[2]; r[3] = rp[3];
    const int* rr = (const int*)r;
#pragma unroll
    for (int j = 0; j < 16; j++) {
        int rv = rr[j];
        if ((g_mT2[rv >> 5] >> (rv & 31)) & 1u) {
            int e = base + j;
            int col = wCols[e];
            int slot = atomicAdd(&g_cntT2[rv], 1);
            if (slot == 0) g_listT2[atomicAdd(&g_nT2, 1)] = rv;
            if (slot < CAP_T2)
                g_bT2[rv * CAP_T2 + slot] = make_int2(col, __float_as_int(wVals[e]));
            atomicOr(&g_mH2[col >> 5], 1u << (col & 31));
        }
    }
}

__global__ void k_p3(const int* __restrict__ wiRows, const int* __restrict__ wiCols,
                     const float* __restrict__ wiVals, const float* __restrict__ diag1) {
    int base = (blockIdx.x * blockDim.x + threadIdx.x) * 16;
    if (base >= EE) return;
    const int4* rp = (const int4*)(wiRows + base);
    int4 r[4];
    r[0] = rp[0]; r[1] = rp[1]; r[2] = rp[2]; r[3] = rp[3];
    const int* rr = (const int*)r;
#pragma unroll
    for (int j = 0; j < 16; j++) {
        int rv = rr[j];
        if ((g_mH2[rv >> 5] >> (rv & 31)) & 1u) {
            int e = base + j;
            int col = wiCols[e];
            float coef = wiVals[e] * diag1[col];
            int slot = atomicAdd(&g_cntX1[rv], 1);
            if (slot == 0) g_listX1[atomicAdd(&g_nX1, 1)] = rv;
            if (slot < CAP_X1)
                g_bX1[rv * CAP_X1 + slot] = make_int2(col, __float_as_int(coef));
            atomicOr(&g_mT1[col >> 5], 1u << (col & 31));
        }
    }
}

__global__ void k_p4(const int* __restrict__ wRows, const int* __restrict__ wCols,
                     const float* __restrict__ wVals) {
    int base = (blockIdx.x * blockDim.x + threadIdx.x) * 16;
    if (base >= EE) return;
    const int4* rp = (const int4*)(wRows + base);
    int4 r[4];
    r[0] = rp[0]; r[1] = rp[1]; r[2] = rp[2]; r[3] = rp[3];
    const int* rr = (const int*)r;
#pragma unroll
    for (int j = 0; j < 16; j++) {
        int rv = rr[j];
        if ((g_mT1[rv >> 5] >> (rv & 31)) & 1u) {
            int e = base + j;
            int slot = atomicAdd(&g_cntT1[rv], 1);
            if (slot == 0) g_listT1[atomicAdd(&g_nT1, 1)] = rv;
            if (slot < CAP_T1)
                g_bT1[rv * CAP_T1 + slot] = make_int2(wCols[e], __float_as_int(wVals[e]));
        }
    }
}

// ---------------- forward compute ----------------
// h1 = x @ W1, dense, layout [n][b][32] fp16. One warp per (n,b).
__global__ void k_h1(const float* __restrict__ x, const float* __restrict__ W1) {
    __shared__ float sW[D1 * D1];
    int t = threadIdx.x;
    for (int i = t; i < D1 * D1; i += blockDim.x) sW[i] = W1[i];
    __syncthreads();
    int w = (blockIdx.x * blockDim.x + t) >> 5;
    int lane = t & 31;
    if (w >= NN * BB) return;
    int n = w >> 2, b = w & 3;
    float xv = x[((size_t)b * NN + n) * D1 + lane];
    float acc = 0.f;
#pragma unroll
    for (int k = 0; k < D1; k++) {
        float xk = __shfl_sync(0xffffffffu, xv, k);
        acc = fmaf(xk, sW[k * D1 + lane], acc);
    }
    g_h1[(size_t)w * D1 + lane] = __float2half(acc);
}

// T1[row] = sum_e v_e * h1[col_e]. One warp per active row (fp16 gather, fp32 accum).
__global__ void k_T1() {
    int lane = threadIdx.x & 31;
    int gw = (blockIdx.x * blockDim.x + threadIdx.x) >> 5;
    int nw = (gridDim.x * blockDim.x) >> 5;
    int b = lane >> 3, q = lane & 7;
    int nact = g_nT1;
    for (int i = gw; i < nact; i += nw) {
        int row = g_listT1[i];
        int c = g_cntT1[row]; if (c > CAP_T1) c = CAP_T1;
        const int2* bk = &g_bT1[row * CAP_T1];
        float4 acc = make_float4(0.f, 0.f, 0.f, 0.f);
        int k = 0;
        for (; k + 4 <= c; k += 4) {
            int2 e0 = __ldg(&bk[k]),     e1 = __ldg(&bk[k + 1]);
            int2 e2 = __ldg(&bk[k + 2]), e3 = __ldg(&bk[k + 3]);
            uint2 u0 = *(const uint2*)&g_h1[((size_t)e0.x * BB + b) * D1 + q * 4];
            uint2 u1 = *(const uint2*)&g_h1[((size_t)e1.x * BB + b) * D1 + q * 4];
            uint2 u2 = *(const uint2*)&g_h1[((size_t)e2.x * BB + b) * D1 + q * 4];
            uint2 u3 = *(const uint2*)&g_h1[((size_t)e3.x * BB + b) * D1 + q * 4];
            float v0 = __int_as_float(e0.y), v1 = __int_as_float(e1.y);
            float v2 = __int_as_float(e2.y), v3 = __int_as_float(e3.y);
            float2 a01, a23;
            a01 = __half22float2(*(__half2*)&u0.x); a23 = __half22float2(*(__half2*)&u0.y);
            acc.x = fmaf(v0, a01.x, acc.x); acc.y = fmaf(v0, a01.y, acc.y);
            acc.z = fmaf(v0, a23.x, acc.z); acc.w = fmaf(v0, a23.y, acc.w);
            a01 = __half22float2(*(__half2*)&u1.x); a23 = __half22float2(*(__half2*)&u1.y);
            acc.x = fmaf(v1, a01.x, acc.x); acc.y = fmaf(v1, a01.y, acc.y);
            acc.z = fmaf(v1, a23.x, acc.z); acc.w = fmaf(v1, a23.y, acc.w);
            a01 = __half22float2(*(__half2*)&u2.x); a23 = __half22float2(*(__half2*)&u2.y);
            acc.x = fmaf(v2, a01.x, acc.x); acc.y = fmaf(v2, a01.y, acc.y);
            acc.z = fmaf(v2, a23.x, acc.z); acc.w = fmaf(v2, a23.y, acc.w);
            a01 = __half22float2(*(__half2*)&u3.x); a23 = __half22float2(*(__half2*)&u3.y);
            acc.x = fmaf(v3, a01.x, acc.x); acc.y = fmaf(v3, a01.y, acc.y);
            acc.z = fmaf(v3, a23.x, acc.z); acc.w = fmaf(v3, a23.y, acc.w);
        }
        for (; k < c; k++) {
            int2 e0 = __ldg(&bk[k]);
            float v = __int_as_float(e0.y);
            uint2 u0 = *(const uint2*)&g_h1[((size_t)e0.x * BB + b) * D1 + q * 4];
            float2 a01 = __half22float2(*(__half2*)&u0.x);
            float2 a23 = __half22float2(*(__half2*)&u0.y);
            acc.x = fmaf(v, a01.x, acc.x); acc.y = fmaf(v, a01.y, acc.y);
            acc.z = fmaf(v, a23.x, acc.z); acc.w = fmaf(v, a23.y, acc.w);
        }
        *(float4*)&g_T1[((size_t)row * BB + b) * D1 + q * 4] = acc;
    }
}

// Fused x1 + h2: x1[n] = leaky(sum coef*T1[col]); h2[n] = x1[n] @ W2 (per active node).
__global__ void k_x1h2(const float* __restrict__ W2) {
    __shared__ float sW[D1 * D2];
    __shared__ float sX[8][BB * D1];   // 8 warps/block, 128 floats each
    int t = threadIdx.x;
    for (int i = t; i < D1 * D2; i += blockDim.x) sW[i] = W2[i];
    __syncthreads();
    int lane = t & 31;
    int wlocal = t >> 5;
    int gw = (blockIdx.x * blockDim.x + t) >> 5;
    int nw = (gridDim.x * blockDim.x) >> 5;
    int b = lane >> 3, q = lane & 7;
    int nact = g_nX1;
    for (int i = gw; i < nact; i += nw) {
        int node = g_listX1[i];
        int c = g_cntX1[node]; if (c > CAP_X1) c = CAP_X1;
        const int2* bk = &g_bX1[node * CAP_X1];
        float4 acc = make_float4(0.f, 0.f, 0.f, 0.f);
        int k = 0;
        for (; k + 2 <= c; k += 2) {
            int2 e0 = __ldg(&bk[k]), e1 = __ldg(&bk[k + 1]);
            float4 t0 = *(const float4*)&g_T1[((size_t)e0.x * BB + b) * D1 + q * 4];
            float4 t1 = *(const float4*)&g_T1[((size_t)e1.x * BB + b) * D1 + q * 4];
            float v0 = __int_as_float(e0.y), v1 = __int_as_float(e1.y);
            acc.x = fmaf(v0, t0.x, acc.x); acc.y = fmaf(v0, t0.y, acc.y);
            acc.z = fmaf(v0, t0.z, acc.z); acc.w = fmaf(v0, t0.w, acc.w);
            acc.x = fmaf(v1, t1.x, acc.x); acc.y = fmaf(v1, t1.y, acc.y);
            acc.z = fmaf(v1, t1.z, acc.z); acc.w = fmaf(v1, t1.w, acc.w);
        }
        for (; k < c; k++) {
            int2 e0 = __ldg(&bk[k]);
            float v = __int_as_float(e0.y);
            float4 tv = *(const float4*)&g_T1[((size_t)e0.x * BB + b) * D1 + q * 4];
            acc.x = fmaf(v, tv.x, acc.x); acc.y = fmaf(v, tv.y, acc.y);
            acc.z = fmaf(v, tv.z, acc.z); acc.w = fmaf(v, tv.w, acc.w);
        }
        acc.x = acc.x > 0.f ? acc.x : NEG * acc.x;
        acc.y = acc.y > 0.f ? acc.y : NEG * acc.y;
        acc.z = acc.z > 0.f ? acc.z : NEG * acc.z;
        acc.w = acc.w > 0.f ? acc.w : NEG * acc.w;
        // stage x1 through smem, then h2 = x1 @ W2
        *(float4*)&sX[wlocal][b * D1 + q * 4] = acc;
        __syncwarp();
        int j = lane & 7;                 // 8 lanes per batch -> 2 outputs each
        const float* xr = &sX[wlocal][b * D1];
        float a0 = 0.f, a1 = 0.f;
#pragma unroll
        for (int kk = 0; kk < D1; kk++) {
            float xv = xr[kk];
            a0 = fmaf(xv, sW[kk * D2 + j], a0);
            a1 = fmaf(xv, sW[kk * D2 + j + 8], a1);
        }
        g_h2[((size_t)node * BB + b) * D2 + j] = a0;
        g_h2[((size_t)node * BB + b) * D2 + j + 8] = a1;
        __syncwarp();
    }
}

// T2[row] = sum_e v_e * h2[col_e]. One warp per active row (16 lanes).
__global__ void k_T2() {
    int lane = threadIdx.x & 31;
    int gw = (blockIdx.x * blockDim.x + threadIdx.x) >> 5;
    int nw = (gridDim.x * blockDim.x) >> 5;
    int nact = g_nT2;
    int b = (lane >> 2) & 3, q = lane & 3;
    for (int i = gw; i < nact; i += nw) {
        int row = g_listT2[i];
        int c = g_cntT2[row]; if (c > CAP_T2) c = CAP_T2;
        if (lane >= 16) continue;
        const int2* bk = &g_bT2[row * CAP_T2];
        float4 acc = make_float4(0.f, 0.f, 0.f, 0.f);
        for (int k = 0; k < c; k++) {
            int2 e0 = __ldg(&bk[k]);
            float v = __int_as_float(e0.y);
            float4 h = *(const float4*)&g_h2[((size_t)e0.x * BB + b) * D2 + q * 4];
            acc.x = fmaf(v, h.x, acc.x); acc.y = fmaf(v, h.y, acc.y);
            acc.z = fmaf(v, h.z, acc.z); acc.w = fmaf(v, h.w, acc.w);
        }
        *(float4*)&g_T2[((size_t)row * BB + b) * D2 + q * 4] = acc;
    }
}

// final: 2 nodes -> leaky -> linear heads -> out (B,2,1)
__global__ void k_out(const float* __restrict__ rw1, const float* __restrict__ rb1,
                      const float* __restrict__ rw2, const float* __restrict__ rb2,
                      float* __restrict__ out) {
    int warp = threadIdx.x >> 5;   // 8 warps: b = warp&3, s = warp>>2
    int lane = threadIdx.x & 31;
    int b = warp & 3, s = warp >> 2;
    int c = g_cntP1[s]; if (c > CAP_P1) c = CAP_P1;
    float acc = 0.f;
    for (int i = 0; i < c; i++) {
        int2 e = g_bP1[s * CAP_P1 + i];
        float coef = __int_as_float(e.y);
        if (lane < D2) acc = fmaf(coef, g_T2[((size_t)e.x * BB + b) * D2 + lane], acc);
    }
    float v = acc > 0.f ? acc : NEG * acc;
    const float* w = s ? rw2 : rw1;
    float y = (lane < D2) ? v * w[lane] : 0.f;
#pragma unroll
    for (int o = 16; o > 0; o >>= 1) y += __shfl_xor_sync(0xffffffffu, y, o);
    if (lane == 0) out[b * 2 + s] = y + (s ? rb2[0] : rb1[0]);
}

// ---------------- launch ----------------
extern "C" void kernel_launch(void* const* d_in, const int* in_sizes, int n_in,
                              void* d_out, int out_size) {
    const int*   wIdx   = (const int*)d_in[0];
    const float* wVal   = (const float*)d_in[1];
    const int*   wiIdx  = (const int*)d_in[2];
    const float* wiVal  = (const float*)d_in[3];
    const float* x      = (const float*)d_in[4];
    const float* W1     = (const float*)d_in[5];
    const float* diag1  = (const float*)d_in[6];
    const float* W2     = (const float*)d_in[7];
    const float* diag2  = (const float*)d_in[8];
    const float* rw1    = (const float*)d_in[9];
    const float* rb1    = (const float*)d_in[10];
    const float* rw2    = (const float*)d_in[11];
    const float* rb2    = (const float*)d_in[12];

    const int* wRows  = wIdx;
    const int* wCols  = wIdx + EE;
    const int* wiRows = wiIdx;
    const int* wiCols = wiIdx + EE;
    float* out = (float*)d_out;

    const int sBlocks = (EE / 16 + 255) / 256;   // 16 edges per thread

    k_zero<<<256, 256>>>();
    k_p1<<<sBlocks, 256>>>(wiRows, wiCols, wiVal, diag2);
    k_p2<<<sBlocks, 256>>>(wRows, wCols, wVal);
    k_p3<<<sBlocks, 256>>>(wiRows, wiCols, wiVal, diag1);
    k_p4<<<sBlocks, 256>>>(wRows, wCols, wVal);
    k_h1<<<(NN * BB * 32 + 255) / 256, 256>>>(x, W1);
    k_T1<<<1024, 256>>>();
    k_x1h2<<<64, 256>>>(W2);
    k_T2<<<16, 256>>>();
    k_out<<<1, 256>>>(rw1, rb1, rw2, rb2, out);
}

// round 4
// speedup vs baseline: 1.2372x; 1.2372x over previous
#include <cuda_runtime.h>
#include <cuda_fp16.h>
#include <cstdint>

// Problem constants (fixed by the dataset)
#define BB 4
#define NN 50000
#define RR 100000
#define EE 1600000
#define D1 32
#define D2 16
#define NEG 0.2f

// Bucket capacities (Poisson lambda=16 R-rows / 32 N-rows; overflow prob < 1e-25)
#define CAP_T1 128
#define CAP_X1 192
#define CAP_T2 128
#define CAP_P1 256

#define MW_R ((RR + 31) / 32)
#define MW_N ((NN + 31) / 32)

#define SCAN_T   (EE / 8)                  // 200000 scan threads (8 edges each)
#define SCAN_B   ((SCAN_T + 255) / 256)    // 782 scan blocks
#define H1_W     (NN * BB)                 // 200000 h1 warps (one per (n,b))
#define H1_B     ((H1_W + 7) / 8)          // 25000 h1 blocks (8 warps/block)
#define H1_CHUNK (H1_B / 4)                // 6250 h1 blocks per scan kernel

// ---------------- device scratch (zero-init at module load; left zeroed per call) ----
__device__ __half g_h1[NN * BB * D1];  // 12.8 MB  [n][b][32] fp16
__device__ float g_T1[RR * BB * D1];   // 51.2 MB  [r][b][32]
__device__ float g_h2[NN * BB * D2];   // 12.8 MB  [n][b][16]
__device__ float g_T2[RR * BB * D2];   // 25.6 MB  [r][b][16]

__device__ int  g_cntT1[RR], g_cntX1[NN], g_cntT2[RR], g_cntP1[2];
__device__ int2 g_bT1[RR * CAP_T1];    // (col, val)
__device__ int2 g_bX1[NN * CAP_X1];    // (col, coef)
__device__ int2 g_bT2[RR * CAP_T2];    // (col, val)
__device__ int2 g_bP1[2 * CAP_P1];     // (col, coef)

__device__ unsigned g_mT1[MW_R], g_mT2[MW_R], g_mH2[MW_N];   // bit flags

// ---------------- h1 chunk: h1[n][b][:] = x[b][n][:] @ W1, one warp per (n,b) -------
__device__ __forceinline__ void h1_block(int vb, const float* __restrict__ x,
                                         const float* __restrict__ W1) {
    __shared__ float sW[D1 * D1];
    int t = threadIdx.x;
    for (int i = t; i < D1 * D1; i += 256) sW[i] = W1[i];
    __syncthreads();
    int w = vb * 8 + (t >> 5);
    if (w >= H1_W) return;
    int lane = t & 31;
    int n = w >> 2, b = w & 3;
    float xv = x[((size_t)b * NN + n) * D1 + lane];
    float acc = 0.f;
#pragma unroll
    for (int k = 0; k < D1; k++) {
        float xk = __shfl_sync(0xffffffffu, xv, k);
        acc = fmaf(xk, sW[k * D1 + lane], acc);
    }
    g_h1[(size_t)w * D1 + lane] = __float2half(acc);
}

// ---------------- scan kernels: scan blocks first, then an h1 chunk ------------------
// S1: wi-edges into the 2 output nodes -> bP1 + mark mT2
__global__ void __launch_bounds__(256) k_s1(const int* __restrict__ wiRows,
        const int* __restrict__ wiCols, const float* __restrict__ wiVals,
        const float* __restrict__ diag2,
        const float* __restrict__ x, const float* __restrict__ W1) {
    if (blockIdx.x >= SCAN_B) { h1_block(blockIdx.x - SCAN_B, x, W1); return; }
    int t = blockIdx.x * 256 + threadIdx.x;
    if (t >= SCAN_T) return;
    int base = t * 8;
    int4 a = __ldg((const int4*)(wiRows + base));
    int4 b4 = __ldg((const int4*)(wiRows + base + 4));
    int r[8] = {a.x, a.y, a.z, a.w, b4.x, b4.y, b4.z, b4.w};
#pragma unroll
    for (int j = 0; j < 8; j++) {
        if (r[j] >= NN - 2) {
            int s = r[j] - (NN - 2);
            int e = base + j;
            int col = __ldg(&wiCols[e]);
            float coef = __ldg(&wiVals[e]) * __ldg(&diag2[col]);
            int slot = atomicAdd(&g_cntP1[s], 1);
            if (slot < CAP_P1) g_bP1[s * CAP_P1 + slot] = make_int2(col, __float_as_int(coef));
            atomicOr(&g_mT2[col >> 5], 1u << (col & 31));
        }
    }
}

// S2: w-edges feeding mT2 rows -> bT2 + mark mH2
__global__ void __launch_bounds__(256) k_s2(const int* __restrict__ wRows,
        const int* __restrict__ wCols, const float* __restrict__ wVals,
        const float* __restrict__ x, const float* __restrict__ W1) {
    if (blockIdx.x >= SCAN_B) { h1_block(blockIdx.x - SCAN_B + H1_CHUNK, x, W1); return; }
    int t = blockIdx.x * 256 + threadIdx.x;
    if (t >= SCAN_T) return;
    int base = t * 8;
    int4 a = __ldg((const int4*)(wRows + base));
    int4 b4 = __ldg((const int4*)(wRows + base + 4));
    int r[8] = {a.x, a.y, a.z, a.w, b4.x, b4.y, b4.z, b4.w};
    unsigned m[8];
#pragma unroll
    for (int j = 0; j < 8; j++) m[j] = __ldg(&g_mT2[r[j] >> 5]);
#pragma unroll
    for (int j = 0; j < 8; j++) {
        if ((m[j] >> (r[j] & 31)) & 1u) {
            int e = base + j;
            int col = __ldg(&wCols[e]);
            int slot = atomicAdd(&g_cntT2[r[j]], 1);
            if (slot < CAP_T2)
                g_bT2[r[j] * CAP_T2 + slot] = make_int2(col, __float_as_int(__ldg(&wVals[e])));
            atomicOr(&g_mH2[col >> 5], 1u << (col & 31));
        }
    }
}

// S3: wi-edges feeding mH2 nodes -> bX1 (coef = val*diag1) + mark mT1
__global__ void __launch_bounds__(256) k_s3(const int* __restrict__ wiRows,
        const int* __restrict__ wiCols, const float* __restrict__ wiVals,
        const float* __restrict__ diag1,
        const float* __restrict__ x, const float* __restrict__ W1) {
    if (blockIdx.x >= SCAN_B) { h1_block(blockIdx.x - SCAN_B + 2 * H1_CHUNK, x, W1); return; }
    int t = blockIdx.x * 256 + threadIdx.x;
    if (t >= SCAN_T) return;
    int base = t * 8;
    int4 a = __ldg((const int4*)(wiRows + base));
    int4 b4 = __ldg((const int4*)(wiRows + base + 4));
    int r[8] = {a.x, a.y, a.z, a.w, b4.x, b4.y, b4.z, b4.w};
    unsigned m[8];
#pragma unroll
    for (int j = 0; j < 8; j++) m[j] = __ldg(&g_mH2[r[j] >> 5]);
#pragma unroll
    for (int j = 0; j < 8; j++) {
        if ((m[j] >> (r[j] & 31)) & 1u) {
            int e = base + j;
            int col = __ldg(&wiCols[e]);
            float coef = __ldg(&wiVals[e]) * __ldg(&diag1[col]);
            int slot = atomicAdd(&g_cntX1[r[j]], 1);
            if (slot < CAP_X1)
                g_bX1[r[j] * CAP_X1 + slot] = make_int2(col, __float_as_int(coef));
            atomicOr(&g_mT1[col >> 5], 1u << (col & 31));
        }
    }
}

// S4: w-edges feeding mT1 rows -> bT1 (28% hit rate: stream cols+vals unconditionally)
__global__ void __launch_bounds__(256) k_s4(const int* __restrict__ wRows,
        const int* __restrict__ wCols, const float* __restrict__ wVals,
        const float* __restrict__ x, const float* __restrict__ W1) {
    if (blockIdx.x >= SCAN_B) { h1_block(blockIdx.x - SCAN_B + 3 * H1_CHUNK, x, W1); return; }
    int t = blockIdx.x * 256 + threadIdx.x;
    if (t >= SCAN_T) return;
    int base = t * 8;
    int4 a = __ldg((const int4*)(wRows + base));
    int4 b4 = __ldg((const int4*)(wRows + base + 4));
    int4 c0 = __ldg((const int4*)(wCols + base));
    int4 c1 = __ldg((const int4*)(wCols + base + 4));
    float4 v0 = __ldg((const float4*)(wVals + base));
    float4 v1 = __ldg((const float4*)(wVals + base + 4));
    int r[8] = {a.x, a.y, a.z, a.w, b4.x, b4.y, b4.z, b4.w};
    int cc[8] = {c0.x, c0.y, c0.z, c0.w, c1.x, c1.y, c1.z, c1.w};
    float vv[8] = {v0.x, v0.y, v0.z, v0.w, v1.x, v1.y, v1.z, v1.w};
    unsigned m[8];
#pragma unroll
    for (int j = 0; j < 8; j++) m[j] = __ldg(&g_mT1[r[j] >> 5]);
#pragma unroll
    for (int j = 0; j < 8; j++) {
        if ((m[j] >> (r[j] & 31)) & 1u) {
            int slot = atomicAdd(&g_cntT1[r[j]], 1);
            if (slot < CAP_T1)
                g_bT1[r[j] * CAP_T1 + slot] = make_int2(cc[j], __float_as_int(vv[j]));
        }
    }
}

// ---------------- T1[row] = sum_e v_e * h1[col_e]; one warp per row, full width ------
__global__ void __launch_bounds__(256) k_T1() {
    int w = (blockIdx.x * 256 + threadIdx.x) >> 5;
    if (w >= RR) return;
    int c = g_cntT1[w];
    if (c == 0) return;
    if (c > CAP_T1) c = CAP_T1;
    int lane = threadIdx.x & 31;
    int b = lane >> 3, q = lane & 7;
    const int2* bk = &g_bT1[w * CAP_T1];
    float4 acc = make_float4(0.f, 0.f, 0.f, 0.f);
    int k = 0;
    for (; k + 4 <= c; k += 4) {
        int2 e0 = __ldg(&bk[k]),     e1 = __ldg(&bk[k + 1]);
        int2 e2 = __ldg(&bk[k + 2]), e3 = __ldg(&bk[k + 3]);
        uint2 u0 = *(const uint2*)&g_h1[((size_t)e0.x * BB + b) * D1 + q * 4];
        uint2 u1 = *(const uint2*)&g_h1[((size_t)e1.x * BB + b) * D1 + q * 4];
        uint2 u2 = *(const uint2*)&g_h1[((size_t)e2.x * BB + b) * D1 + q * 4];
        uint2 u3 = *(const uint2*)&g_h1[((size_t)e3.x * BB + b) * D1 + q * 4];
        float v0 = __int_as_float(e0.y), v1 = __int_as_float(e1.y);
        float v2 = __int_as_float(e2.y), v3 = __int_as_float(e3.y);
        float2 a01, a23;
        a01 = __half22float2(*(__half2*)&u0.x); a23 = __half22float2(*(__half2*)&u0.y);
        acc.x = fmaf(v0, a01.x, acc.x); acc.y = fmaf(v0, a01.y, acc.y);
        acc.z = fmaf(v0, a23.x, acc.z); acc.w = fmaf(v0, a23.y, acc.w);
        a01 = __half22float2(*(__half2*)&u1.x); a23 = __half22float2(*(__half2*)&u1.y);
        acc.x = fmaf(v1, a01.x, acc.x); acc.y = fmaf(v1, a01.y, acc.y);
        acc.z = fmaf(v1, a23.x, acc.z); acc.w = fmaf(v1, a23.y, acc.w);
        a01 = __half22float2(*(__half2*)&u2.x); a23 = __half22float2(*(__half2*)&u2.y);
        acc.x = fmaf(v2, a01.x, acc.x); acc.y = fmaf(v2, a01.y, acc.y);
        acc.z = fmaf(v2, a23.x, acc.z); acc.w = fmaf(v2, a23.y, acc.w);
        a01 = __half22float2(*(__half2*)&u3.x); a23 = __half22float2(*(__half2*)&u3.y);
        acc.x = fmaf(v3, a01.x, acc.x); acc.y = fmaf(v3, a01.y, acc.y);
        acc.z = fmaf(v3, a23.x, acc.z); acc.w = fmaf(v3, a23.y, acc.w);
    }
    for (; k < c; k++) {
        int2 e0 = __ldg(&bk[k]);
        float v = __int_as_float(e0.y);
        uint2 u0 = *(const uint2*)&g_h1[((size_t)e0.x * BB + b) * D1 + q * 4];
        float2 a01 = __half22float2(*(__half2*)&u0.x);
        float2 a23 = __half22float2(*(__half2*)&u0.y);
        acc.x = fmaf(v, a01.x, acc.x); acc.y = fmaf(v, a01.y, acc.y);
        acc.z = fmaf(v, a23.x, acc.z); acc.w = fmaf(v, a23.y, acc.w);
    }
    *(float4*)&g_T1[((size_t)w * BB + b) * D1 + q * 4] = acc;
}

// ---------------- fused x1 + h2, one warp per node, full width -----------------------
__global__ void __launch_bounds__(256) k_x1h2(const float* __restrict__ W2) {
    __shared__ float sW[D1 * D2];
    __shared__ float sX[8][BB * D1];
    int t = threadIdx.x;
    for (int i = t; i < D1 * D2; i += 256) sW[i] = W2[i];
    __syncthreads();
    int node = (blockIdx.x * 256 + t) >> 5;
    if (node >= NN) return;
    int c = g_cntX1[node];
    if (c == 0) return;
    if (c > CAP_X1) c = CAP_X1;
    int lane = t & 31;
    int wlocal = t >> 5;
    int b = lane >> 3, q = lane & 7;
    const int2* bk = &g_bX1[node * CAP_X1];
    float4 acc = make_float4(0.f, 0.f, 0.f, 0.f);
    int k = 0;
    for (; k + 2 <= c; k += 2) {
        int2 e0 = __ldg(&bk[k]), e1 = __ldg(&bk[k + 1]);
        float4 t0 = *(const float4*)&g_T1[((size_t)e0.x * BB + b) * D1 + q * 4];
        float4 t1 = *(const float4*)&g_T1[((size_t)e1.x * BB + b) * D1 + q * 4];
        float v0 = __int_as_float(e0.y), v1 = __int_as_float(e1.y);
        acc.x = fmaf(v0, t0.x, acc.x); acc.y = fmaf(v0, t0.y, acc.y);
        acc.z = fmaf(v0, t0.z, acc.z); acc.w = fmaf(v0, t0.w, acc.w);
        acc.x = fmaf(v1, t1.x, acc.x); acc.y = fmaf(v1, t1.y, acc.y);
        acc.z = fmaf(v1, t1.z, acc.z); acc.w = fmaf(v1, t1.w, acc.w);
    }
    for (; k < c; k++) {
        int2 e0 = __ldg(&bk[k]);
        float v = __int_as_float(e0.y);
        float4 tv = *(const float4*)&g_T1[((size_t)e0.x * BB + b) * D1 + q * 4];
        acc.x = fmaf(v, tv.x, acc.x); acc.y = fmaf(v, tv.y, acc.y);
        acc.z = fmaf(v, tv.z, acc.z); acc.w = fmaf(v, tv.w, acc.w);
    }
    acc.x = acc.x > 0.f ? acc.x : NEG * acc.x;
    acc.y = acc.y > 0.f ? acc.y : NEG * acc.y;
    acc.z = acc.z > 0.f ? acc.z : NEG * acc.z;
    acc.w = acc.w > 0.f ? acc.w : NEG * acc.w;
    *(float4*)&sX[wlocal][b * D1 + q * 4] = acc;
    __syncwarp();
    int j = lane & 7;
    const float* xr = &sX[wlocal][b * D1];
    float a0 = 0.f, a1 = 0.f;
#pragma unroll
    for (int kk = 0; kk < D1; kk++) {
        float xv = xr[kk];
        a0 = fmaf(xv, sW[kk * D2 + j], a0);
        a1 = fmaf(xv, sW[kk * D2 + j + 8], a1);
    }
    g_h2[((size_t)node * BB + b) * D2 + j] = a0;
    g_h2[((size_t)node * BB + b) * D2 + j + 8] = a1;
}

// ---------------- T2[row] = sum_e v_e * h2[col_e]; one warp per row, full width ------
__global__ void __launch_bounds__(256) k_T2() {
    int w = (blockIdx.x * 256 + threadIdx.x) >> 5;
    if (w >= RR) return;
    int c = g_cntT2[w];
    if (c == 0) return;
    if (c > CAP_T2) c = CAP_T2;
    int lane = threadIdx.x & 31;
    if (lane >= 16) return;
    int b = lane >> 2, q = lane & 3;
    const int2* bk = &g_bT2[w * CAP_T2];
    float4 acc = make_float4(0.f, 0.f, 0.f, 0.f);
    for (int k = 0; k < c; k++) {
        int2 e0 = __ldg(&bk[k]);
        float v = __int_as_float(e0.y);
        float4 h = *(const float4*)&g_h2[((size_t)e0.x * BB + b) * D2 + q * 4];
        acc.x = fmaf(v, h.x, acc.x); acc.y = fmaf(v, h.y, acc.y);
        acc.z = fmaf(v, h.z, acc.z); acc.w = fmaf(v, h.w, acc.w);
    }
    *(float4*)&g_T2[((size_t)w * BB + b) * D2 + q * 4] = acc;
}

// ---------------- final heads + tail zeroing (state left clean for next call) --------
__global__ void __launch_bounds__(256) k_outz(const float* __restrict__ rw1,
        const float* __restrict__ rb1, const float* __restrict__ rw2,
        const float* __restrict__ rb2, float* __restrict__ out) {
    if (blockIdx.x == 0) {
        int warp = threadIdx.x >> 5;   // 8 warps: b = warp&3, s = warp>>2
        int lane = threadIdx.x & 31;
        int b = warp & 3, s = warp >> 2;
        int c = g_cntP1[s]; if (c > CAP_P1) c = CAP_P1;
        float acc = 0.f;
        for (int i = 0; i < c; i++) {
            int2 e = g_bP1[s * CAP_P1 + i];
            float coef = __int_as_float(e.y);
            if (lane < D2) acc = fmaf(coef, g_T2[((size_t)e.x * BB + b) * D2 + lane], acc);
        }
        float v = acc > 0.f ? acc : NEG * acc;
        const float* w = s ? rw2 : rw1;
        float y = (lane < D2) ? v * w[lane] : 0.f;
#pragma unroll
        for (int o = 16; o > 0; o >>= 1) y += __shfl_xor_sync(0xffffffffu, y, o);
        if (lane == 0) out[b * 2 + s] = y + (s ? rb2[0] : rb1[0]);
        __syncthreads();                       // all warps done reading g_cntP1
        if (threadIdx.x < 2) g_cntP1[threadIdx.x] = 0;
    } else {
        int i0 = (blockIdx.x - 1) * 256 + threadIdx.x;
        const int stride = 64 * 256;
        for (int i = i0; i < RR; i += stride) { g_cntT1[i] = 0; g_cntT2[i] = 0; }
        for (int i = i0; i < NN; i += stride) g_cntX1[i] = 0;
        for (int i = i0; i < MW_R; i += stride) { g_mT1[i] = 0u; g_mT2[i] = 0u; }
        for (int i = i0; i < MW_N; i += stride) g_mH2[i] = 0u;
    }
}

// ---------------- launch ----------------
extern "C" void kernel_launch(void* const* d_in, const int* in_sizes, int n_in,
                              void* d_out, int out_size) {
    const int*   wIdx   = (const int*)d_in[0];
    const float* wVal   = (const float*)d_in[1];
    const int*   wiIdx  = (const int*)d_in[2];
    const float* wiVal  = (const float*)d_in[3];
    const float* x      = (const float*)d_in[4];
    const float* W1     = (const float*)d_in[5];
    const float* diag1  = (const float*)d_in[6];
    const float* W2     = (const float*)d_in[7];
    const float* diag2  = (const float*)d_in[8];
    const float* rw1    = (const float*)d_in[9];
    const float* rb1    = (const float*)d_in[10];
    const float* rw2    = (const float*)d_in[11];
    const float* rb2    = (const float*)d_in[12];

    const int* wRows  = wIdx;
    const int* wCols  = wIdx + EE;
    const int* wiRows = wiIdx;
    const int* wiCols = wiIdx + EE;
    float* out = (float*)d_out;

    const int mixGrid = SCAN_B + H1_CHUNK;   // 782 + 6250

    k_s1<<<mixGrid, 256>>>(wiRows, wiCols, wiVal, diag2, x, W1);
    k_s2<<<mixGrid, 256>>>(wRows, wCols, wVal, x, W1);
    k_s3<<<mixGrid, 256>>>(wiRows, wiCols, wiVal, diag1, x, W1);
    k_s4<<<mixGrid, 256>>>(wRows, wCols, wVal, x, W1);
    k_T1<<<(RR * 32 + 255) / 256, 256>>>();
    k_x1h2<<<(NN * 32 + 255) / 256, 256>>>(W2);
    k_T2<<<(RR * 32 + 255) / 256, 256>>>();
    k_outz<<<65, 256>>>(rw1, rb1, rw2, rb2, out);
}